// round 5
// baseline (speedup 1.0000x reference)
#include <cuda_runtime.h>

#define H 1024
#define B 8
#define T 4096

// Scratch: v[b][i] = sum_j W[i][j] * context[b][j]
__device__ float g_v[B * H];

// Kernel 1: 256 blocks x 256 threads, 4 W rows per block.
// ctx (32 KB) staged in smem ONCE per block -> L2 ctx traffic drops 8 MiB
// total (was 32 MiB with one block per row). W streamed once from DRAM.
__global__ void __launch_bounds__(256) compute_v_kernel(
    const float* __restrict__ W,     // (H, H)
    const float* __restrict__ ctx)   // (B, H)
{
    __shared__ float sctx[B * H];    // 32 KB
    __shared__ float red[8][9];      // [warp][batch] (+1 pad)

    const int tid  = threadIdx.x;
    const int lane = tid & 31;
    const int warp = tid >> 5;

#pragma unroll
    for (int k = 0; k < 8; k++)
        reinterpret_cast<float4*>(sctx)[tid + 256 * k] =
            reinterpret_cast<const float4*>(ctx)[tid + 256 * k];
    __syncthreads();

#pragma unroll
    for (int r = 0; r < 4; r++) {
        const int row = blockIdx.x * 4 + r;
        const float4 w4 = reinterpret_cast<const float4*>(W + (size_t)row * H)[tid];

        float acc[B];
#pragma unroll
        for (int b = 0; b < B; b++) {
            const float4 c = reinterpret_cast<const float4*>(sctx + b * H)[tid];
            acc[b] = w4.x * c.x + w4.y * c.y + w4.z * c.z + w4.w * c.w;
        }
#pragma unroll
        for (int b = 0; b < B; b++) {
#pragma unroll
            for (int o = 16; o; o >>= 1)
                acc[b] += __shfl_xor_sync(0xFFFFFFFFu, acc[b], o);
        }
        if (lane == 0) {
#pragma unroll
            for (int b = 0; b < B; b++) red[warp][b] = acc[b];
        }
        __syncthreads();
        if (tid < B) {
            float s = 0.0f;
#pragma unroll
            for (int w = 0; w < 8; w++) s += red[w][tid];
            g_v[tid * H + row] = s;
        }
        __syncthreads();
    }

    // All g_v writes by this block done: let the dependent grid proceed.
    cudaTriggerProgrammaticLaunchCompletion();
}

// Kernel 2: one (b,t) row per warp, 256-thread blocks (8 rows/block),
// 4096 blocks. States LDGs are front-batched BEFORE the PDL grid-dependency
// sync (they don't depend on g_v), so wave 1 overlaps compute_v.
// v is pulled via __ldg inside the FMA loop (L1/L2-hot). 2 accumulators.
__global__ void __launch_bounds__(256) score_kernel(
    const float* __restrict__ states,  // (B, T, H)
    const float* __restrict__ bias,    // (1,)
    float* __restrict__ out)           // (B*T,)
{
    const int lane = threadIdx.x & 31;
    const int row  = blockIdx.x * 8 + (threadIdx.x >> 5);
    const int b    = row >> 12;        // row / T

    const float4* s4 = reinterpret_cast<const float4*>(states + (size_t)row * H);

    // Front-batch the 8 DRAM loads (one full 4 KB row per warp)
    float4 x[8];
#pragma unroll
    for (int k = 0; k < 8; k++) x[k] = s4[lane + 32 * k];

    // Wait for compute_v's g_v to be valid (overlapped with the loads above)
    cudaGridDependencySynchronize();

    const float4* v4 = reinterpret_cast<const float4*>(g_v + b * H);
    float acc0 = 0.0f, acc1 = 0.0f;
#pragma unroll
    for (int k = 0; k < 8; k += 2) {
        const float4 w0 = __ldg(v4 + lane + 32 * k);
        const float4 w1 = __ldg(v4 + lane + 32 * (k + 1));
        acc0 += x[k].x * w0.x + x[k].y * w0.y + x[k].z * w0.z + x[k].w * w0.w;
        acc1 += x[k+1].x * w1.x + x[k+1].y * w1.y + x[k+1].z * w1.z + x[k+1].w * w1.w;
    }
    float acc = acc0 + acc1;

#pragma unroll
    for (int o = 16; o; o >>= 1)
        acc += __shfl_xor_sync(0xFFFFFFFFu, acc, o);

    if (lane == 0) out[row] = acc + bias[0];
}

extern "C" void kernel_launch(void* const* d_in, const int* in_sizes, int n_in,
                              void* d_out, int out_size)
{
    const float* states = (const float*)d_in[0];   // (B, T, H)
    const float* ctx    = (const float*)d_in[1];   // (B, H)
    const float* W      = (const float*)d_in[2];   // (1, H, H)
    const float* bias   = (const float*)d_in[3];   // (1,)
    float* out = (float*)d_out;                    // (B, T, 1)

    compute_v_kernel<<<H / 4, 256>>>(W, ctx);

    cudaLaunchConfig_t cfg = {};
    cfg.gridDim  = dim3((B * T) / 8);
    cfg.blockDim = dim3(256);
    cfg.dynamicSmemBytes = 0;
    cfg.stream = 0;
    cudaLaunchAttribute attr[1];
    attr[0].id = cudaLaunchAttributeProgrammaticStreamSerialization;
    attr[0].val.programmaticStreamSerializationAllowed = 1;
    cfg.attrs = attr;
    cfg.numAttrs = 1;
    cudaLaunchKernelEx(&cfg, score_kernel, states, bias, (float*)d_out);
}

// round 6
// speedup vs baseline: 1.1164x; 1.1164x over previous
#include <cuda_runtime.h>
#include <cstdint>

#define H 1024
#define B 8
#define T 4096

#define TILE_ROWS   8
#define TILE_FLOATS (TILE_ROWS * H)          // 8192
#define TILE_BYTES  (TILE_FLOATS * 4)        // 32768
#define N_TILES     ((B * T) / TILE_ROWS)    // 4096
#define SCORE_GRID  (148 * 3)
#define SMEM_BYTES  (2 * TILE_BYTES + 16)    // 2 stages + 2 mbarriers

__device__ float g_v[B * H];

__device__ __forceinline__ uint32_t smem_u32(const void* p) {
    uint32_t a;
    asm("{ .reg .u64 t; cvta.to.shared.u64 t, %1; cvt.u32.u64 %0, t; }" : "=r"(a) : "l"(p));
    return a;
}

__device__ __forceinline__ void mbar_init(uint32_t mbar, uint32_t cnt) {
    asm volatile("mbarrier.init.shared.b64 [%0], %1;" :: "r"(mbar), "r"(cnt) : "memory");
}
__device__ __forceinline__ void mbar_expect_tx(uint32_t mbar, uint32_t bytes) {
    asm volatile("mbarrier.arrive.expect_tx.shared.b64 _, [%0], %1;" :: "r"(mbar), "r"(bytes) : "memory");
}
__device__ __forceinline__ void bulk_g2s(uint32_t dst, const void* src, uint32_t bytes, uint32_t mbar) {
    asm volatile("cp.async.bulk.shared::cluster.global.mbarrier::complete_tx::bytes [%0], [%1], %2, [%3];"
                 :: "r"(dst), "l"(src), "r"(bytes), "r"(mbar) : "memory");
}
__device__ __forceinline__ void mbar_wait(uint32_t mbar, uint32_t parity) {
    asm volatile(
        "{\n\t"
        ".reg .pred P;\n\t"
        "W_%=:\n\t"
        "mbarrier.try_wait.parity.acquire.cta.shared::cta.b64 P, [%0], %1, 0x989680;\n\t"
        "@P bra D_%=;\n\t"
        "bra W_%=;\n\t"
        "D_%=:\n\t"
        "}" :: "r"(mbar), "r"(parity) : "memory");
}

// ───────────────────────── Kernel 1: v = W @ ctx ─────────────────────────
// 256 blocks x 256 threads, 4 W rows per block. ctx staged in smem once
// (8 MiB total L2 traffic); the 4 W-row loads are front-batched.
__global__ void __launch_bounds__(256) compute_v_kernel(
    const float* __restrict__ W, const float* __restrict__ ctx)
{
    __shared__ float sctx[B * H];    // 32 KB
    __shared__ float red[4][8][9];   // [row][warp][batch]

    const int tid  = threadIdx.x;
    const int lane = tid & 31;
    const int warp = tid >> 5;

#pragma unroll
    for (int k = 0; k < 8; k++)
        reinterpret_cast<float4*>(sctx)[tid + 256 * k] =
            reinterpret_cast<const float4*>(ctx)[tid + 256 * k];

    float4 w[4];
#pragma unroll
    for (int r = 0; r < 4; r++)
        w[r] = reinterpret_cast<const float4*>(W + (size_t)(blockIdx.x * 4 + r) * H)[tid];

    __syncthreads();

#pragma unroll
    for (int r = 0; r < 4; r++) {
        float acc[B];
#pragma unroll
        for (int b = 0; b < B; b++) {
            const float4 c = reinterpret_cast<const float4*>(sctx + b * H)[tid];
            acc[b] = w[r].x * c.x + w[r].y * c.y + w[r].z * c.z + w[r].w * c.w;
        }
#pragma unroll
        for (int b = 0; b < B; b++) {
#pragma unroll
            for (int o = 16; o; o >>= 1)
                acc[b] += __shfl_xor_sync(0xFFFFFFFFu, acc[b], o);
        }
        if (lane == 0) {
#pragma unroll
            for (int b = 0; b < B; b++) red[r][warp][b] = acc[b];
        }
    }
    __syncthreads();

    if (tid < 4 * B) {               // 32 threads: (row r, batch b)
        const int r = tid >> 3, b = tid & 7;
        float s = 0.0f;
#pragma unroll
        for (int wi = 0; wi < 8; wi++) s += red[r][wi][b];
        g_v[b * H + blockIdx.x * 4 + r] = s;
    }
    cudaTriggerProgrammaticLaunchCompletion();
}

// ───────────────────────── Kernel 2: scores ─────────────────────────
// Persistent 444 blocks. Double-buffered cp.async.bulk pipeline: 32 KB
// (8-row) tiles stream into smem via mbarrier completion; warp w computes
// row w of each tile (LDS.128 dot v + shuffle reduce). Memory issue is
// decoupled from the compute/reduce tails.
__global__ void __launch_bounds__(256) score_kernel(
    const float* __restrict__ states, const float* __restrict__ bias,
    float* __restrict__ out)
{
    extern __shared__ float smem[];
    float* buf = smem;                                   // 2 x 8192 floats
    uint32_t mbar0 = smem_u32(smem + 2 * TILE_FLOATS);   // 2 mbarriers
    uint32_t mbar1 = mbar0 + 8;

    const int tid  = threadIdx.x;
    const int lane = tid & 31;
    const int warp = tid >> 5;
    const int stride = gridDim.x;

    if (tid == 0) { mbar_init(mbar0, 1); mbar_init(mbar1, 1); }
    __syncthreads();

    int tile = blockIdx.x;

    // Prologue: stage 0 <- first tile (states is not written by compute_v,
    // so this may issue before the PDL dependency resolves)
    if (tid == 0) {
        mbar_expect_tx(mbar0, TILE_BYTES);
        bulk_g2s(smem_u32(buf), states + (size_t)tile * TILE_FLOATS, TILE_BYTES, mbar0);
    }
    cudaGridDependencySynchronize();   // g_v valid after this
    const float bb = bias[0];

    int i = 0;
    for (; tile < N_TILES; tile += stride, i++) {
        const int cur = i & 1;

        // Prefetch next tile into the other stage (its previous consumer
        // finished before the __syncthreads at the end of iteration i-1)
        const int nxt = tile + stride;
        if (nxt < N_TILES && tid == 0) {
            const uint32_t mb = (i & 1) ? mbar0 : mbar1;   // stage (i+1)&1
            mbar_expect_tx(mb, TILE_BYTES);
            bulk_g2s(smem_u32(buf + ((i + 1) & 1) * TILE_FLOATS),
                     states + (size_t)nxt * TILE_FLOATS, TILE_BYTES, mb);
        }

        mbar_wait(cur ? mbar1 : mbar0, (i >> 1) & 1);

        // Compute: warp w owns row w of this tile
        const int row = tile * TILE_ROWS + warp;
        const float4* v4 = reinterpret_cast<const float4*>(g_v + ((row >> 12) << 10));
        const float4* x4 = reinterpret_cast<const float4*>(buf + cur * TILE_FLOATS + warp * H);

        float acc0 = 0.0f, acc1 = 0.0f;
#pragma unroll
        for (int k = 0; k < 8; k += 2) {
            const float4 x0 = x4[lane + 32 * k];
            const float4 x1 = x4[lane + 32 * (k + 1)];
            const float4 w0 = __ldg(v4 + lane + 32 * k);
            const float4 w1 = __ldg(v4 + lane + 32 * (k + 1));
            acc0 += x0.x * w0.x + x0.y * w0.y + x0.z * w0.z + x0.w * w0.w;
            acc1 += x1.x * w1.x + x1.y * w1.y + x1.z * w1.z + x1.w * w1.w;
        }
        float acc = acc0 + acc1;
#pragma unroll
        for (int o = 16; o; o >>= 1)
            acc += __shfl_xor_sync(0xFFFFFFFFu, acc, o);
        if (lane == 0) out[row] = acc + bb;

        __syncthreads();   // all warps done with stage `cur`
    }
}

extern "C" void kernel_launch(void* const* d_in, const int* in_sizes, int n_in,
                              void* d_out, int out_size)
{
    const float* states = (const float*)d_in[0];   // (B, T, H)
    const float* ctx    = (const float*)d_in[1];   // (B, H)
    const float* W      = (const float*)d_in[2];   // (1, H, H)
    const float* bias   = (const float*)d_in[3];   // (1,)

    compute_v_kernel<<<H / 4, 256>>>(W, ctx);

    cudaFuncSetAttribute(score_kernel,
                         cudaFuncAttributeMaxDynamicSharedMemorySize, SMEM_BYTES);

    cudaLaunchConfig_t cfg = {};
    cfg.gridDim  = dim3(SCORE_GRID);
    cfg.blockDim = dim3(256);
    cfg.dynamicSmemBytes = SMEM_BYTES;
    cfg.stream = 0;
    cudaLaunchAttribute attr[1];
    attr[0].id = cudaLaunchAttributeProgrammaticStreamSerialization;
    attr[0].val.programmaticStreamSerializationAllowed = 1;
    cfg.attrs = attr;
    cfg.numAttrs = 1;
    cudaLaunchKernelEx(&cfg, score_kernel, states, bias, (float*)d_out);
}

// round 7
// speedup vs baseline: 1.1250x; 1.0077x over previous
#include <cuda_runtime.h>
#include <cstdint>

#define H 1024
#define B 8
#define T 4096

#define TILE_ROWS   8
#define TILE_FLOATS (TILE_ROWS * H)          // 8192
#define TILE_BYTES  (TILE_FLOATS * 4)        // 32768
#define N_TILES     ((B * T) / TILE_ROWS)    // 4096
#define N_STAGES    3
#define SCORE_GRID  (148 * 2)
#define SMEM_BYTES  (N_STAGES * TILE_BYTES + 32)   // 3 stages + mbarriers

__device__ float g_v[B * H];

__device__ __forceinline__ uint32_t smem_u32(const void* p) {
    uint32_t a;
    asm("{ .reg .u64 t; cvta.to.shared.u64 t, %1; cvt.u32.u64 %0, t; }" : "=r"(a) : "l"(p));
    return a;
}
__device__ __forceinline__ void mbar_init(uint32_t mbar, uint32_t cnt) {
    asm volatile("mbarrier.init.shared.b64 [%0], %1;" :: "r"(mbar), "r"(cnt) : "memory");
}
__device__ __forceinline__ void mbar_expect_tx(uint32_t mbar, uint32_t bytes) {
    asm volatile("mbarrier.arrive.expect_tx.shared.b64 _, [%0], %1;" :: "r"(mbar), "r"(bytes) : "memory");
}
__device__ __forceinline__ void bulk_g2s(uint32_t dst, const void* src, uint32_t bytes, uint32_t mbar) {
    asm volatile("cp.async.bulk.shared::cluster.global.mbarrier::complete_tx::bytes [%0], [%1], %2, [%3];"
                 :: "r"(dst), "l"(src), "r"(bytes), "r"(mbar) : "memory");
}
__device__ __forceinline__ void mbar_wait(uint32_t mbar, uint32_t parity) {
    asm volatile(
        "{\n\t"
        ".reg .pred P;\n\t"
        "W_%=:\n\t"
        "mbarrier.try_wait.parity.acquire.cta.shared::cta.b64 P, [%0], %1, 0x989680;\n\t"
        "@P bra D_%=;\n\t"
        "bra W_%=;\n\t"
        "D_%=:\n\t"
        "}" :: "r"(mbar), "r"(parity) : "memory");
}

// ───────────────────────── Kernel 1: v = W @ ctx ─────────────────────────
// (unchanged from R6 — fully hidden under score's prologue via PDL)
__global__ void __launch_bounds__(256) compute_v_kernel(
    const float* __restrict__ W, const float* __restrict__ ctx)
{
    __shared__ float sctx[B * H];
    __shared__ float red[4][8][9];

    const int tid  = threadIdx.x;
    const int lane = tid & 31;
    const int warp = tid >> 5;

#pragma unroll
    for (int k = 0; k < 8; k++)
        reinterpret_cast<float4*>(sctx)[tid + 256 * k] =
            reinterpret_cast<const float4*>(ctx)[tid + 256 * k];

    float4 w[4];
#pragma unroll
    for (int r = 0; r < 4; r++)
        w[r] = reinterpret_cast<const float4*>(W + (size_t)(blockIdx.x * 4 + r) * H)[tid];

    __syncthreads();

#pragma unroll
    for (int r = 0; r < 4; r++) {
        float acc[B];
#pragma unroll
        for (int b = 0; b < B; b++) {
            const float4 c = reinterpret_cast<const float4*>(sctx + b * H)[tid];
            acc[b] = w[r].x * c.x + w[r].y * c.y + w[r].z * c.z + w[r].w * c.w;
        }
#pragma unroll
        for (int b = 0; b < B; b++) {
#pragma unroll
            for (int o = 16; o; o >>= 1)
                acc[b] += __shfl_xor_sync(0xFFFFFFFFu, acc[b], o);
        }
        if (lane == 0) {
#pragma unroll
            for (int b = 0; b < B; b++) red[r][warp][b] = acc[b];
        }
    }
    __syncthreads();

    if (tid < 4 * B) {
        const int r = tid >> 3, b = tid & 7;
        float s = 0.0f;
#pragma unroll
        for (int wi = 0; wi < 8; wi++) s += red[r][wi][b];
        g_v[b * H + blockIdx.x * 4 + r] = s;
    }
    cudaTriggerProgrammaticLaunchCompletion();
}

// ───────────────────────── Kernel 2: scores ─────────────────────────
// Persistent 296 blocks, 3-stage (96 KB) cp.async.bulk pipeline: 2 copies
// always in flight per block. Warp w computes row w of each 8-row tile.
__global__ void __launch_bounds__(256) score_kernel(
    const float* __restrict__ states, const float* __restrict__ bias,
    float* __restrict__ out)
{
    extern __shared__ float smem[];
    float* buf = smem;                                        // 3 x 8192 floats
    const uint32_t mbar_base = smem_u32(smem + N_STAGES * TILE_FLOATS);

    const int tid  = threadIdx.x;
    const int lane = tid & 31;
    const int warp = tid >> 5;
    const int stride = gridDim.x;

    if (tid == 0) {
#pragma unroll
        for (int s = 0; s < N_STAGES; s++) mbar_init(mbar_base + 8 * s, 1);
    }
    __syncthreads();

    // Prologue: fill stages 0 and 1 (states doesn't depend on g_v)
    if (tid == 0) {
#pragma unroll
        for (int p = 0; p < 2; p++) {
            const int t = blockIdx.x + p * stride;
            if (t < N_TILES) {
                mbar_expect_tx(mbar_base + 8 * p, TILE_BYTES);
                bulk_g2s(smem_u32(buf + p * TILE_FLOATS),
                         states + (size_t)t * TILE_FLOATS, TILE_BYTES, mbar_base + 8 * p);
            }
        }
    }
    cudaGridDependencySynchronize();     // g_v valid after this
    const float bb = bias[0];

    int i = 0;
    int stage = 0, parity = 0;
    for (int tile = blockIdx.x; tile < N_TILES; tile += stride, i++) {
        mbar_wait(mbar_base + 8 * stage, parity);

        const int row = tile * TILE_ROWS + warp;
        const float4* v4 = reinterpret_cast<const float4*>(g_v + ((row >> 12) << 10));
        const float4* x4 = reinterpret_cast<const float4*>(buf + stage * TILE_FLOATS + warp * H);

        float acc0 = 0.0f, acc1 = 0.0f;
#pragma unroll
        for (int k = 0; k < 8; k += 2) {
            const float4 x0 = x4[lane + 32 * k];
            const float4 x1 = x4[lane + 32 * (k + 1)];
            const float4 w0 = __ldg(v4 + lane + 32 * k);
            const float4 w1 = __ldg(v4 + lane + 32 * (k + 1));
            acc0 += x0.x * w0.x + x0.y * w0.y + x0.z * w0.z + x0.w * w0.w;
            acc1 += x1.x * w1.x + x1.y * w1.y + x1.z * w1.z + x1.w * w1.w;
        }
        float acc = acc0 + acc1;
#pragma unroll
        for (int o = 16; o; o >>= 1)
            acc += __shfl_xor_sync(0xFFFFFFFFu, acc, o);
        if (lane == 0) out[row] = acc + bb;

        __syncthreads();   // all warps done with this stage -> reusable

        // Refill this stage with tile i+N_STAGES... actually tile+2*stride
        // goes into stage (i+2)%3 == (i-1)%3; refill the stage we just freed
        // with the tile 3 strides ahead? No: copies were prefetched 2 ahead,
        // so the stage just consumed (i) is refilled with tile i+3... wait:
        // stages hold i, i+1, i+2 (i+2 issued at end of iteration i-1... )
        // Invariant kept below: at end of iteration i, issue copy for tile
        // (i+2)*stride into stage (i+2)%3 — the stage freed at iteration i-1.
        const int nxt = tile + 2 * stride;
        if (tid == 0 && nxt < N_TILES) {
            const int ns = (i + 2) % N_STAGES;
            mbar_expect_tx(mbar_base + 8 * ns, TILE_BYTES);
            bulk_g2s(smem_u32(buf + ns * TILE_FLOATS),
                     states + (size_t)nxt * TILE_FLOATS, TILE_BYTES, mbar_base + 8 * ns);
        }

        if (++stage == N_STAGES) { stage = 0; parity ^= 1; }
    }
}

extern "C" void kernel_launch(void* const* d_in, const int* in_sizes, int n_in,
                              void* d_out, int out_size)
{
    const float* states = (const float*)d_in[0];   // (B, T, H)
    const float* ctx    = (const float*)d_in[1];   // (B, H)
    const float* W      = (const float*)d_in[2];   // (1, H, H)
    const float* bias   = (const float*)d_in[3];   // (1,)

    compute_v_kernel<<<H / 4, 256>>>(W, ctx);

    cudaFuncSetAttribute(score_kernel,
                         cudaFuncAttributeMaxDynamicSharedMemorySize, SMEM_BYTES);

    cudaLaunchConfig_t cfg = {};
    cfg.gridDim  = dim3(SCORE_GRID);
    cfg.blockDim = dim3(256);
    cfg.dynamicSmemBytes = SMEM_BYTES;
    cfg.stream = 0;
    cudaLaunchAttribute attr[1];
    attr[0].id = cudaLaunchAttributeProgrammaticStreamSerialization;
    attr[0].val.programmaticStreamSerializationAllowed = 1;
    cfg.attrs = attr;
    cfg.numAttrs = 1;
    cudaLaunchKernelEx(&cfg, score_kernel, states, bias, (float*)d_out);
}